// round 11
// baseline (speedup 1.0000x reference)
#include <cuda_runtime.h>
#include <cstdint>
#include <math.h>

#define Bsz 4
#define Ssz 512
#define Dsz 1024
#define Hsz 16
#define HDsz 64
#define Lsz 6
#define Fsz 4096
#define Vsz 32000
#define NTOK (Bsz*Ssz)

#define NEG_INF (-1.0f/0.0f)

// ---------------- scratch (no allocation allowed; __device__ globals) ----------------
__device__ float g_X[NTOK*Dsz];
__device__ float g_Q[NTOK*Dsz];
__device__ float g_K[NTOK*Dsz];
__device__ float g_V[NTOK*Dsz];
__device__ float g_CTX[NTOK*Dsz];
__device__ float g_T[NTOK*Dsz];
__device__ float g_FF[(size_t)NTOK*Fsz];
// transposed (tf32-rounded) weights
__device__ float g_WTq[(size_t)Lsz*Dsz*Dsz];
__device__ float g_WTk[(size_t)Lsz*Dsz*Dsz];
__device__ float g_WTv[(size_t)Lsz*Dsz*Dsz];
__device__ float g_WTo[(size_t)Lsz*Dsz*Dsz];
__device__ float g_WT1[(size_t)Lsz*Dsz*Fsz];
__device__ float g_WT2[(size_t)Lsz*Fsz*Dsz];
__device__ float g_WTout[(size_t)Vsz*Dsz];

__device__ __forceinline__ uint32_t smem_u32(const void* p) {
    uint32_t a;
    asm("{ .reg .u64 t; cvta.to.shared.u64 t, %1; cvt.u32.u64 %0, t; }" : "=r"(a) : "l"(p));
    return a;
}

// ================= weight transpose (+ tf32 rounding) =================
__global__ void transpose_tf32(const float* __restrict__ in, float* __restrict__ out,
                               int K, int N)
{
    __shared__ float tile[32][33];
    size_t off = (size_t)blockIdx.z * K * N;
    in += off; out += off;
    int tx = threadIdx.x, ty = threadIdx.y;
    int n = blockIdx.x * 32 + tx;
    int k0 = blockIdx.y * 32;
#pragma unroll
    for (int i = ty; i < 32; i += 8)
        tile[i][tx] = in[(size_t)(k0 + i) * N + n];
    __syncthreads();
    int k = k0 + tx;
    int n0 = blockIdx.x * 32;
#pragma unroll
    for (int i = ty; i < 32; i += 8) {
        float v = tile[tx][i];
        asm("cvt.rna.tf32.f32 %0, %0;" : "+f"(v));
        out[(size_t)(n0 + i) * K + k] = v;
    }
}

// ================= tf32 mma.sync GEMM (R8 proven core, 128x128) =================
#define GPAD 36
#define GEMM_SMEM (4*128*GPAD*4)

__device__ __forceinline__ void mma_tf32(float* d, const uint32_t* a, const uint32_t* b)
{
    asm volatile("mma.sync.aligned.m16n8k8.row.col.f32.tf32.tf32.f32 "
        "{%0,%1,%2,%3}, {%4,%5,%6,%7}, {%8,%9}, {%0,%1,%2,%3};"
        : "+f"(d[0]), "+f"(d[1]), "+f"(d[2]), "+f"(d[3])
        : "r"(a[0]), "r"(a[1]), "r"(a[2]), "r"(a[3]), "r"(b[0]), "r"(b[1]));
}

__device__ __forceinline__ void ldsm4(uint32_t* r, uint32_t addr)
{
    asm volatile("ldmatrix.sync.aligned.m8n8.x4.shared.b16 {%0,%1,%2,%3}, [%4];"
        : "=r"(r[0]), "=r"(r[1]), "=r"(r[2]), "=r"(r[3]) : "r"(addr));
}

__device__ __forceinline__ void gemm_mma_core(const float* __restrict__ A,
        const float* __restrict__ WT, const float* __restrict__ bias,
        float* __restrict__ C, int N, int K, int relu, int bx, int by)
{
    extern __shared__ float sm[];
    float* Abuf[2] = { sm,              sm + 2 * 128 * GPAD };
    float* Bbuf[2] = { sm + 128 * GPAD, sm + 3 * 128 * GPAD };

    int tid = threadIdx.x, lane = tid & 31, wid = tid >> 5;
    int m0 = (wid & 1) * 64;
    int n0 = (wid >> 1) * 32;

    const float* Ap = A  + (size_t)(by * 128) * K;
    const float* Bp = WT + (size_t)(bx * 128) * K;

    int gr = tid >> 3;
    int gc = (tid & 7) * 4;

    uint32_t aoff = ((uint32_t)(m0 + (lane & 15)) * GPAD + ((lane >> 4) << 2)) * 4u;
    uint32_t boff = ((uint32_t)(n0 + ((lane >> 4) << 3) + (lane & 7)) * GPAD
                     + (((lane >> 3) & 1) << 2)) * 4u;

    float4 av[4], bv[4];
#pragma unroll
    for (int i = 0; i < 4; i++) {
        av[i] = *(const float4*)(Ap + (size_t)(gr + 32 * i) * K + gc);
        bv[i] = *(const float4*)(Bp + (size_t)(gr + 32 * i) * K + gc);
        asm("cvt.rna.tf32.f32 %0, %0;" : "+f"(av[i].x));
        asm("cvt.rna.tf32.f32 %0, %0;" : "+f"(av[i].y));
        asm("cvt.rna.tf32.f32 %0, %0;" : "+f"(av[i].z));
        asm("cvt.rna.tf32.f32 %0, %0;" : "+f"(av[i].w));
    }
#pragma unroll
    for (int i = 0; i < 4; i++) {
        *(float4*)&Abuf[0][(gr + 32 * i) * GPAD + gc] = av[i];
        *(float4*)&Bbuf[0][(gr + 32 * i) * GPAD + gc] = bv[i];
    }
    __syncthreads();

    float acc[4][4][4] = {};
    int nch = K >> 5;
    for (int kt = 0; kt < nch; kt++) {
        int cur = kt & 1;
        if (kt + 1 < nch) {
            int k0 = (kt + 1) << 5;
#pragma unroll
            for (int i = 0; i < 4; i++) {
                av[i] = *(const float4*)(Ap + (size_t)(gr + 32 * i) * K + k0 + gc);
                bv[i] = *(const float4*)(Bp + (size_t)(gr + 32 * i) * K + k0 + gc);
                asm("cvt.rna.tf32.f32 %0, %0;" : "+f"(av[i].x));
                asm("cvt.rna.tf32.f32 %0, %0;" : "+f"(av[i].y));
                asm("cvt.rna.tf32.f32 %0, %0;" : "+f"(av[i].z));
                asm("cvt.rna.tf32.f32 %0, %0;" : "+f"(av[i].w));
            }
        }
        uint32_t aU = smem_u32(Abuf[cur]);
        uint32_t bU = smem_u32(Bbuf[cur]);
#pragma unroll
        for (int ks = 0; ks < 4; ks++) {
            uint32_t kbyte = (uint32_t)ks * 32u;
            uint32_t bfr[2][4];
            ldsm4(bfr[0], bU + boff + kbyte);
            ldsm4(bfr[1], bU + boff + 16u * GPAD * 4u + kbyte);
#pragma unroll
            for (int mt = 0; mt < 4; mt++) {
                uint32_t afr[4];
                ldsm4(afr, aU + aoff + (uint32_t)mt * 16u * GPAD * 4u + kbyte);
#pragma unroll
                for (int nt = 0; nt < 4; nt++)
                    mma_tf32(acc[mt][nt], afr, &bfr[nt >> 1][(nt & 1) * 2]);
            }
        }
        if (kt + 1 < nch) {
            int nxt = cur ^ 1;
#pragma unroll
            for (int i = 0; i < 4; i++) {
                *(float4*)&Abuf[nxt][(gr + 32 * i) * GPAD + gc] = av[i];
                *(float4*)&Bbuf[nxt][(gr + 32 * i) * GPAD + gc] = bv[i];
            }
            __syncthreads();
        }
    }

    int lg = lane >> 2, lt = lane & 3;
#pragma unroll
    for (int mt = 0; mt < 4; mt++) {
        int r1 = by * 128 + m0 + mt * 16 + lg;
#pragma unroll
        for (int nt = 0; nt < 4; nt++) {
            int cb = bx * 128 + n0 + nt * 8 + lt * 2;
            float2 bb = *(const float2*)(bias + cb);
            float2 v0, v1;
            v0.x = acc[mt][nt][0] + bb.x; v0.y = acc[mt][nt][1] + bb.y;
            v1.x = acc[mt][nt][2] + bb.x; v1.y = acc[mt][nt][3] + bb.y;
            if (relu) {
                v0.x = fmaxf(v0.x, 0.f); v0.y = fmaxf(v0.y, 0.f);
                v1.x = fmaxf(v1.x, 0.f); v1.y = fmaxf(v1.y, 0.f);
            }
            *(float2*)(C + (size_t)r1 * N + cb)       = v0;
            *(float2*)(C + (size_t)(r1 + 8) * N + cb) = v1;
        }
    }
}

__global__ __launch_bounds__(256, 2)
void gemm_mma(const float* __restrict__ A, const float* __restrict__ WT,
              const float* __restrict__ bias, float* __restrict__ C,
              int N, int K, int relu)
{
    gemm_mma_core(A, WT, bias, C, N, K, relu, blockIdx.y, blockIdx.x);
}

__global__ __launch_bounds__(256, 2)
void gemm_mma_qkv(const float* __restrict__ A,
                  const float* __restrict__ WTq, const float* __restrict__ bq, float* __restrict__ Q,
                  const float* __restrict__ WTk, const float* __restrict__ bk, float* __restrict__ Kp,
                  const float* __restrict__ WTv, const float* __restrict__ bv, float* __restrict__ V)
{
    const float* W = (blockIdx.z == 0) ? WTq : (blockIdx.z == 1) ? WTk : WTv;
    const float* b = (blockIdx.z == 0) ? bq  : (blockIdx.z == 1) ? bk  : bv;
    float* C       = (blockIdx.z == 0) ? Q   : (blockIdx.z == 1) ? Kp  : V;
    gemm_mma_core(A, W, b, C, Dsz, Dsz, 0, blockIdx.y, blockIdx.x);
}

// ================= 64x128-tile variant (3 CTAs/SM) for under-occupied GEMMs =================
// 8 warps as 2m x 4n, warp tile 32x32. Layout: [A0|B0|A1|B1], A=64 rows, B=128 rows.
#define GEMM64_SMEM (384*GPAD*4)

__global__ __launch_bounds__(256, 3)
void gemm64_mma(const float* __restrict__ A, const float* __restrict__ WT,
                const float* __restrict__ bias, float* __restrict__ C,
                int N, int K, int relu)
{
    extern __shared__ float sm[];
    float* Abuf[2] = { sm,             sm + 192 * GPAD };
    float* Bbuf[2] = { sm + 64 * GPAD, sm + 256 * GPAD };
    int bx = blockIdx.y, by = blockIdx.x;

    int tid = threadIdx.x, lane = tid & 31, wid = tid >> 5;
    int m0 = (wid & 1) * 32;
    int n0 = (wid >> 1) * 32;

    const float* Ap = A  + (size_t)(by * 64) * K;
    const float* Bp = WT + (size_t)(bx * 128) * K;

    int gr = tid >> 3;            // 0..31
    int gc = (tid & 7) * 4;       // 0..28

    uint32_t aoff = ((uint32_t)(m0 + (lane & 15)) * GPAD + ((lane >> 4) << 2)) * 4u;
    uint32_t boff = ((uint32_t)(n0 + ((lane >> 4) << 3) + (lane & 7)) * GPAD
                     + (((lane >> 3) & 1) << 2)) * 4u;

    // prologue: chunk 0
    float4 av[2], bv[4];
#pragma unroll
    for (int i = 0; i < 2; i++) {
        av[i] = *(const float4*)(Ap + (size_t)(gr + 32 * i) * K + gc);
        asm("cvt.rna.tf32.f32 %0, %0;" : "+f"(av[i].x));
        asm("cvt.rna.tf32.f32 %0, %0;" : "+f"(av[i].y));
        asm("cvt.rna.tf32.f32 %0, %0;" : "+f"(av[i].z));
        asm("cvt.rna.tf32.f32 %0, %0;" : "+f"(av[i].w));
    }
#pragma unroll
    for (int i = 0; i < 4; i++)
        bv[i] = *(const float4*)(Bp + (size_t)(gr + 32 * i) * K + gc);
#pragma unroll
    for (int i = 0; i < 2; i++)
        *(float4*)&Abuf[0][(gr + 32 * i) * GPAD + gc] = av[i];
#pragma unroll
    for (int i = 0; i < 4; i++)
        *(float4*)&Bbuf[0][(gr + 32 * i) * GPAD + gc] = bv[i];
    __syncthreads();

    float acc[2][4][4] = {};
    int nch = K >> 5;
    for (int kt = 0; kt < nch; kt++) {
        int cur = kt & 1;
        if (kt + 1 < nch) {
            int k0 = (kt + 1) << 5;
#pragma unroll
            for (int i = 0; i < 2; i++) {
                av[i] = *(const float4*)(Ap + (size_t)(gr + 32 * i) * K + k0 + gc);
                asm("cvt.rna.tf32.f32 %0, %0;" : "+f"(av[i].x));
                asm("cvt.rna.tf32.f32 %0, %0;" : "+f"(av[i].y));
                asm("cvt.rna.tf32.f32 %0, %0;" : "+f"(av[i].z));
                asm("cvt.rna.tf32.f32 %0, %0;" : "+f"(av[i].w));
            }
#pragma unroll
            for (int i = 0; i < 4; i++)
                bv[i] = *(const float4*)(Bp + (size_t)(gr + 32 * i) * K + k0 + gc);
        }
        uint32_t aU = smem_u32(Abuf[cur]);
        uint32_t bU = smem_u32(Bbuf[cur]);
#pragma unroll
        for (int ks = 0; ks < 4; ks++) {
            uint32_t kbyte = (uint32_t)ks * 32u;
            uint32_t bfr[2][4];
            ldsm4(bfr[0], bU + boff + kbyte);
            ldsm4(bfr[1], bU + boff + 16u * GPAD * 4u + kbyte);
#pragma unroll
            for (int mt = 0; mt < 2; mt++) {
                uint32_t afr[4];
                ldsm4(afr, aU + aoff + (uint32_t)mt * 16u * GPAD * 4u + kbyte);
#pragma unroll
                for (int nt = 0; nt < 4; nt++)
                    mma_tf32(acc[mt][nt], afr, &bfr[nt >> 1][(nt & 1) * 2]);
            }
        }
        if (kt + 1 < nch) {
            int nxt = cur ^ 1;
#pragma unroll
            for (int i = 0; i < 2; i++)
                *(float4*)&Abuf[nxt][(gr + 32 * i) * GPAD + gc] = av[i];
#pragma unroll
            for (int i = 0; i < 4; i++)
                *(float4*)&Bbuf[nxt][(gr + 32 * i) * GPAD + gc] = bv[i];
            __syncthreads();
        }
    }

    int lg = lane >> 2, lt = lane & 3;
#pragma unroll
    for (int mt = 0; mt < 2; mt++) {
        int r1 = by * 64 + m0 + mt * 16 + lg;
#pragma unroll
        for (int nt = 0; nt < 4; nt++) {
            int cb = bx * 128 + n0 + nt * 8 + lt * 2;
            float2 bb = *(const float2*)(bias + cb);
            float2 v0, v1;
            v0.x = acc[mt][nt][0] + bb.x; v0.y = acc[mt][nt][1] + bb.y;
            v1.x = acc[mt][nt][2] + bb.x; v1.y = acc[mt][nt][3] + bb.y;
            if (relu) {
                v0.x = fmaxf(v0.x, 0.f); v0.y = fmaxf(v0.y, 0.f);
                v1.x = fmaxf(v1.x, 0.f); v1.y = fmaxf(v1.y, 0.f);
            }
            *(float2*)(C + (size_t)r1 * N + cb)       = v0;
            *(float2*)(C + (size_t)(r1 + 8) * N + cb) = v1;
        }
    }
}

// ---------------- embedding * sqrt(D) + sinusoidal PE ----------------
__global__ void embed_kernel(const int* __restrict__ ids, const float* __restrict__ emb,
                             float* __restrict__ X)
{
    int row = blockIdx.x;
    int s   = row % Ssz;
    int id  = ids[row];
    const float* e = emb + (size_t)id * Dsz;
    float* x = X + (size_t)row * Dsz;
    const float nl = -logf(10000.0f) / (float)Dsz;
    for (int d = threadIdx.x; d < Dsz; d += blockDim.x) {
        int i = d >> 1;
        float div = expf((float)(2 * i) * nl);
        float ang = (float)s * div;
        float pe  = (d & 1) ? cosf(ang) : sinf(ang);
        x[d] = e[d] * 32.0f + pe;
    }
}

// ---------------- fused flash attention ----------------
#define ATT_SMEM (4*64*65*4)

__global__ __launch_bounds__(256)
void attn_fused(const float* __restrict__ Q, const float* __restrict__ K,
                const float* __restrict__ V, const int* __restrict__ ids,
                float* __restrict__ CTX)
{
    extern __shared__ float smf[];
    float* qs = smf;
    float* ks = smf + 64 * 65;
    float* vs = smf + 2 * 64 * 65;
    float* ps = smf + 3 * 64 * 65;
    __shared__ float padv[64];
    __shared__ float s_l[64];
    __shared__ int s_any;

    int it = blockIdx.x, bh = blockIdx.y;
    int b = bh >> 4, h = bh & 15;
    int i0 = it * 64;
    int tid = threadIdx.x, tx = tid & 15, ty = tid >> 4;

    const float* Qp = Q + ((size_t)(b * Ssz + i0)) * Dsz + h * HDsz;
    for (int i = tid; i < 64 * 64; i += 256) {
        int r = i >> 6, d = i & 63;
        qs[d * 65 + r] = Qp[(size_t)r * Dsz + d];
    }

    float m[4], l[4], acc[4][4];
#pragma unroll
    for (int i = 0; i < 4; i++) {
        m[i] = -1e30f; l[i] = 0.0f;
#pragma unroll
        for (int n = 0; n < 4; n++) acc[i][n] = 0.0f;
    }

    for (int jt = 0; jt <= it; jt++) {
        int j0 = jt * 64;
        const float* Kp = K + ((size_t)(b * Ssz + j0)) * Dsz + h * HDsz;
        const float* Vp = V + ((size_t)(b * Ssz + j0)) * Dsz + h * HDsz;
        for (int i = tid; i < 64 * 64; i += 256) {
            int r = i >> 6, d = i & 63;
            ks[d * 65 + r] = Kp[(size_t)r * Dsz + d];
            vs[r * 65 + d] = Vp[(size_t)r * Dsz + d];
        }
        if (tid < 64)
            padv[tid] = (ids[b * Ssz + j0 + tid] == 0) ? NEG_INF : 0.0f;
        __syncthreads();

        float s[4][4] = {};
#pragma unroll 8
        for (int d = 0; d < HDsz; d++) {
            float a[4], w[4];
#pragma unroll
            for (int i = 0; i < 4; i++) a[i] = qs[d * 65 + ty * 4 + i];
#pragma unroll
            for (int j = 0; j < 4; j++) w[j] = ks[d * 65 + tx * 4 + j];
#pragma unroll
            for (int i = 0; i < 4; i++)
#pragma unroll
                for (int j = 0; j < 4; j++)
                    s[i][j] = fmaf(a[i], w[j], s[i][j]);
        }
        bool diag = (jt == it);
#pragma unroll
        for (int i = 0; i < 4; i++) {
            int ri = i0 + ty * 4 + i;
            float rmax = NEG_INF;
#pragma unroll
            for (int j = 0; j < 4; j++) {
                float v = s[i][j] * 0.125f + padv[tx * 4 + j];
                if (diag && (j0 + tx * 4 + j) > ri) v = NEG_INF;
                s[i][j] = v;
                rmax = fmaxf(rmax, v);
            }
#pragma unroll
            for (int o = 8; o > 0; o >>= 1)
                rmax = fmaxf(rmax, __shfl_xor_sync(0xffffffffu, rmax, o));
            float mn = fmaxf(m[i], fmaxf(rmax, -1e30f));
            float sc = expf(m[i] - mn);
            l[i] *= sc;
#pragma unroll
            for (int n = 0; n < 4; n++) acc[i][n] *= sc;
            float rs = 0.0f;
#pragma unroll
            for (int j = 0; j < 4; j++) {
                float p = expf(s[i][j] - mn);
                s[i][j] = p;
                rs += p;
            }
#pragma unroll
            for (int o = 8; o > 0; o >>= 1)
                rs += __shfl_xor_sync(0xffffffffu, rs, o);
            l[i] += rs;
            m[i] = mn;
        }
#pragma unroll
        for (int i = 0; i < 4; i++)
#pragma unroll
            for (int j = 0; j < 4; j++)
                ps[(tx * 4 + j) * 65 + ty * 4 + i] = s[i][j];
        __syncthreads();
#pragma unroll 8
        for (int kk = 0; kk < 64; kk++) {
            float a[4], w[4];
#pragma unroll
            for (int i = 0; i < 4; i++) a[i] = ps[kk * 65 + ty * 4 + i];
#pragma unroll
            for (int n = 0; n < 4; n++) w[n] = vs[kk * 65 + tx * 4 + n];
#pragma unroll
            for (int i = 0; i < 4; i++)
#pragma unroll
                for (int n = 0; n < 4; n++)
                    acc[i][n] = fmaf(a[i], w[n], acc[i][n]);
        }
        __syncthreads();
    }

    if (tx == 0)
#pragma unroll
        for (int i = 0; i < 4; i++) s_l[ty * 4 + i] = l[i];
    if (tid == 0) s_any = 0;
    __syncthreads();
    if (tid < 64 && s_l[tid] == 0.0f) s_any = 1;
    __syncthreads();

#pragma unroll
    for (int i = 0; i < 4; i++) {
        if (l[i] > 0.0f) {
            float inv = 1.0f / l[i];
            float* o = CTX + ((size_t)(b * Ssz + i0 + ty * 4 + i)) * Dsz + h * HDsz + tx * 4;
#pragma unroll
            for (int n = 0; n < 4; n++) o[n] = acc[i][n] * inv;
        }
    }

    if (s_any) {
        int part = tid >> 6, n = tid & 63;
        const float* Vb = V + ((size_t)(b * Ssz)) * Dsz + h * HDsz;
        float ssum = 0.0f;
        for (int j = part * 128; j < part * 128 + 128; j++)
            ssum += Vb[(size_t)j * Dsz + n];
        ps[tid] = ssum;
        __syncthreads();
        if (tid < 64)
            padv[tid] = (ps[tid] + ps[tid + 64] + ps[tid + 128] + ps[tid + 192]) * (1.0f / 512.0f);
        __syncthreads();
#pragma unroll
        for (int i = 0; i < 4; i++) {
            if (l[i] == 0.0f) {
                float* o = CTX + ((size_t)(b * Ssz + i0 + ty * 4 + i)) * Dsz + h * HDsz + tx * 4;
#pragma unroll
                for (int n2 = 0; n2 < 4; n2++) o[n2] = padv[tx * 4 + n2];
            }
        }
    }
}

// ---------------- X = LayerNorm(X + T) * g + b ----------------
__global__ void add_ln(const float* __restrict__ X, const float* __restrict__ T,
                       const float* __restrict__ g, const float* __restrict__ bb,
                       float* __restrict__ O)
{
    int row = blockIdx.x;
    int t = threadIdx.x;
    const float* x = X + (size_t)row * Dsz;
    const float* tt = T + (size_t)row * Dsz;
    float y[4];
    float s = 0.0f;
#pragma unroll
    for (int k = 0; k < 4; k++) {
        int d = t + k * 256;
        y[k] = x[d] + tt[d];
        s += y[k];
    }
    __shared__ float red[256];
    red[t] = s;
    __syncthreads();
    for (int st = 128; st > 0; st >>= 1) {
        if (t < st) red[t] += red[t + st];
        __syncthreads();
    }
    float mean = red[0] * (1.0f / Dsz);
    __syncthreads();
    float ss = 0.0f;
#pragma unroll
    for (int k = 0; k < 4; k++) {
        float d = y[k] - mean;
        ss += d * d;
    }
    red[t] = ss;
    __syncthreads();
    for (int st = 128; st > 0; st >>= 1) {
        if (t < st) red[t] += red[t + st];
        __syncthreads();
    }
    float var = red[0] * (1.0f / Dsz);
    float inv = rsqrtf(var + 1e-5f);
    float* o = O + (size_t)row * Dsz;
#pragma unroll
    for (int k = 0; k < 4; k++) {
        int d = t + k * 256;
        o[d] = (y[k] - mean) * inv * g[d] + bb[d];
    }
}

// ---------------- launch ----------------
extern "C" void kernel_launch(void* const* d_in, const int* in_sizes, int n_in,
                              void* d_out, int out_size)
{
    const int*   ids    = (const int*)  d_in[0];
    const float* emb    = (const float*)d_in[2];
    const float* Wq     = (const float*)d_in[3];
    const float* bq     = (const float*)d_in[4];
    const float* Wk     = (const float*)d_in[5];
    const float* bk     = (const float*)d_in[6];
    const float* Wv     = (const float*)d_in[7];
    const float* bv     = (const float*)d_in[8];
    const float* Wo     = (const float*)d_in[9];
    const float* bo     = (const float*)d_in[10];
    const float* g1     = (const float*)d_in[11];
    const float* b1n    = (const float*)d_in[12];
    const float* W1     = (const float*)d_in[13];
    const float* b1f    = (const float*)d_in[14];
    const float* W2     = (const float*)d_in[15];
    const float* b2f    = (const float*)d_in[16];
    const float* g2     = (const float*)d_in[17];
    const float* b2n    = (const float*)d_in[18];
    const float* Wout   = (const float*)d_in[19];
    const float* bout   = (const float*)d_in[20];
    float* out = (float*)d_out;

    float *X, *Q, *K, *V, *CTX, *T, *FF;
    float *WTq, *WTk, *WTv, *WTo, *WT1, *WT2, *WTout;
    cudaGetSymbolAddress((void**)&X,   g_X);
    cudaGetSymbolAddress((void**)&Q,   g_Q);
    cudaGetSymbolAddress((void**)&K,   g_K);
    cudaGetSymbolAddress((void**)&V,   g_V);
    cudaGetSymbolAddress((void**)&CTX, g_CTX);
    cudaGetSymbolAddress((void**)&T,   g_T);
    cudaGetSymbolAddress((void**)&FF,  g_FF);
    cudaGetSymbolAddress((void**)&WTq, g_WTq);
    cudaGetSymbolAddress((void**)&WTk, g_WTk);
    cudaGetSymbolAddress((void**)&WTv, g_WTv);
    cudaGetSymbolAddress((void**)&WTo, g_WTo);
    cudaGetSymbolAddress((void**)&WT1, g_WT1);
    cudaGetSymbolAddress((void**)&WT2, g_WT2);
    cudaGetSymbolAddress((void**)&WTout, g_WTout);

    cudaFuncSetAttribute(gemm_mma,     cudaFuncAttributeMaxDynamicSharedMemorySize, GEMM_SMEM);
    cudaFuncSetAttribute(gemm_mma_qkv, cudaFuncAttributeMaxDynamicSharedMemorySize, GEMM_SMEM);
    cudaFuncSetAttribute(gemm64_mma,   cudaFuncAttributeMaxDynamicSharedMemorySize, GEMM64_SMEM);
    cudaFuncSetAttribute(attn_fused,   cudaFuncAttributeMaxDynamicSharedMemorySize, ATT_SMEM);

    // weight transposes (+tf32 rounding), recomputed every replay (deterministic)
    transpose_tf32<<<dim3(Dsz/32, Dsz/32, Lsz), dim3(32, 8)>>>(Wq, WTq, Dsz, Dsz);
    transpose_tf32<<<dim3(Dsz/32, Dsz/32, Lsz), dim3(32, 8)>>>(Wk, WTk, Dsz, Dsz);
    transpose_tf32<<<dim3(Dsz/32, Dsz/32, Lsz), dim3(32, 8)>>>(Wv, WTv, Dsz, Dsz);
    transpose_tf32<<<dim3(Dsz/32, Dsz/32, Lsz), dim3(32, 8)>>>(Wo, WTo, Dsz, Dsz);
    transpose_tf32<<<dim3(Fsz/32, Dsz/32, Lsz), dim3(32, 8)>>>(W1, WT1, Dsz, Fsz);
    transpose_tf32<<<dim3(Dsz/32, Fsz/32, Lsz), dim3(32, 8)>>>(W2, WT2, Fsz, Dsz);
    transpose_tf32<<<dim3(Vsz/32, Dsz/32, 1),   dim3(32, 8)>>>(Wout, WTout, Dsz, Vsz);

    embed_kernel<<<NTOK, 256>>>(ids, emb, X);

    for (int l = 0; l < Lsz; l++) {
        const float* wtq = WTq + (size_t)l * Dsz * Dsz;
        const float* wtk = WTk + (size_t)l * Dsz * Dsz;
        const float* wtv = WTv + (size_t)l * Dsz * Dsz;
        const float* wto = WTo + (size_t)l * Dsz * Dsz;
        const float* wt1 = WT1 + (size_t)l * Dsz * Fsz;
        const float* wt2 = WT2 + (size_t)l * Fsz * Dsz;
        const float* bql = bq + (size_t)l * Dsz;
        const float* bkl = bk + (size_t)l * Dsz;
        const float* bvl = bv + (size_t)l * Dsz;
        const float* bol = bo + (size_t)l * Dsz;
        const float* b1fl = b1f + (size_t)l * Fsz;
        const float* b2fl = b2f + (size_t)l * Dsz;
        const float* g1l = g1 + (size_t)l * Dsz;
        const float* b1nl = b1n + (size_t)l * Dsz;
        const float* g2l = g2 + (size_t)l * Dsz;
        const float* b2nl = b2n + (size_t)l * Dsz;

        gemm_mma_qkv<<<dim3(NTOK/128, Dsz/128, 3), 256, GEMM_SMEM>>>(
            X, wtq, bql, Q, wtk, bkl, K, wtv, bvl, V);

        attn_fused<<<dim3(Ssz/64, Bsz*Hsz), 256, ATT_SMEM>>>(Q, K, V, ids, CTX);

        gemm64_mma<<<dim3(NTOK/64, Dsz/128), 256, GEMM64_SMEM>>>(CTX, wto, bol, T, Dsz, Dsz, 0);
        add_ln<<<NTOK, 256>>>(X, T, g1l, b1nl, X);

        gemm_mma<<<dim3(NTOK/128, Fsz/128), 256, GEMM_SMEM>>>(X, wt1, b1fl, FF, Fsz, Dsz, 1);
        gemm64_mma<<<dim3(NTOK/64, Dsz/128), 256, GEMM64_SMEM>>>(FF, wt2, b2fl, T, Dsz, Fsz, 0);
        add_ln<<<NTOK, 256>>>(X, T, g2l, b2nl, X);
    }

    gemm_mma<<<dim3(NTOK/128, Vsz/128), 256, GEMM_SMEM>>>(X, WTout, bout, out, Vsz, Dsz, 0);
}

// round 12
// speedup vs baseline: 1.0307x; 1.0307x over previous
#include <cuda_runtime.h>
#include <cstdint>
#include <math.h>

#define Bsz 4
#define Ssz 512
#define Dsz 1024
#define Hsz 16
#define HDsz 64
#define Lsz 6
#define Fsz 4096
#define Vsz 32000
#define NTOK (Bsz*Ssz)

#define NEG_INF (-1.0f/0.0f)

// ---------------- scratch (no allocation allowed; __device__ globals) ----------------
__device__ float g_X[NTOK*Dsz];
__device__ float g_Q[NTOK*Dsz];
__device__ float g_K[NTOK*Dsz];
__device__ float g_V[NTOK*Dsz];
__device__ float g_CTX[NTOK*Dsz];
__device__ float g_T[NTOK*Dsz];
__device__ float g_FF[(size_t)NTOK*Fsz];
// transposed (tf32-rounded) weights
__device__ float g_WTq[(size_t)Lsz*Dsz*Dsz];
__device__ float g_WTk[(size_t)Lsz*Dsz*Dsz];
__device__ float g_WTv[(size_t)Lsz*Dsz*Dsz];
__device__ float g_WTo[(size_t)Lsz*Dsz*Dsz];
__device__ float g_WT1[(size_t)Lsz*Dsz*Fsz];
__device__ float g_WT2[(size_t)Lsz*Fsz*Dsz];
__device__ float g_WTout[(size_t)Vsz*Dsz];

__device__ __forceinline__ uint32_t smem_u32(const void* p) {
    uint32_t a;
    asm("{ .reg .u64 t; cvta.to.shared.u64 t, %1; cvt.u32.u64 %0, t; }" : "=r"(a) : "l"(p));
    return a;
}

// ================= weight transpose (+ tf32 rounding) =================
__global__ void transpose_tf32(const float* __restrict__ in, float* __restrict__ out,
                               int K, int N)
{
    __shared__ float tile[32][33];
    size_t off = (size_t)blockIdx.z * K * N;
    in += off; out += off;
    int tx = threadIdx.x, ty = threadIdx.y;
    int n = blockIdx.x * 32 + tx;
    int k0 = blockIdx.y * 32;
#pragma unroll
    for (int i = ty; i < 32; i += 8)
        tile[i][tx] = in[(size_t)(k0 + i) * N + n];
    __syncthreads();
    int k = k0 + tx;
    int n0 = blockIdx.x * 32;
#pragma unroll
    for (int i = ty; i < 32; i += 8) {
        float v = tile[tx][i];
        asm("cvt.rna.tf32.f32 %0, %0;" : "+f"(v));
        out[(size_t)(n0 + i) * K + k] = v;
    }
}

// ================= tf32 mma.sync GEMM (R8 proven core, 128x128) =================
#define GPAD 36
#define GEMM_SMEM (4*128*GPAD*4)

__device__ __forceinline__ void mma_tf32(float* d, const uint32_t* a, const uint32_t* b)
{
    asm volatile("mma.sync.aligned.m16n8k8.row.col.f32.tf32.tf32.f32 "
        "{%0,%1,%2,%3}, {%4,%5,%6,%7}, {%8,%9}, {%0,%1,%2,%3};"
        : "+f"(d[0]), "+f"(d[1]), "+f"(d[2]), "+f"(d[3])
        : "r"(a[0]), "r"(a[1]), "r"(a[2]), "r"(a[3]), "r"(b[0]), "r"(b[1]));
}

__device__ __forceinline__ void ldsm4(uint32_t* r, uint32_t addr)
{
    asm volatile("ldmatrix.sync.aligned.m8n8.x4.shared.b16 {%0,%1,%2,%3}, [%4];"
        : "=r"(r[0]), "=r"(r[1]), "=r"(r[2]), "=r"(r[3]) : "r"(addr));
}

__device__ __forceinline__ void gemm_mma_core(const float* __restrict__ A,
        const float* __restrict__ WT, const float* __restrict__ bias,
        float* __restrict__ C, int N, int K, int relu, int bx, int by)
{
    extern __shared__ float sm[];
    float* Abuf[2] = { sm,              sm + 2 * 128 * GPAD };
    float* Bbuf[2] = { sm + 128 * GPAD, sm + 3 * 128 * GPAD };

    int tid = threadIdx.x, lane = tid & 31, wid = tid >> 5;
    int m0 = (wid & 1) * 64;
    int n0 = (wid >> 1) * 32;

    const float* Ap = A  + (size_t)(by * 128) * K;
    const float* Bp = WT + (size_t)(bx * 128) * K;

    int gr = tid >> 3;
    int gc = (tid & 7) * 4;

    uint32_t aoff = ((uint32_t)(m0 + (lane & 15)) * GPAD + ((lane >> 4) << 2)) * 4u;
    uint32_t boff = ((uint32_t)(n0 + ((lane >> 4) << 3) + (lane & 7)) * GPAD
                     + (((lane >> 3) & 1) << 2)) * 4u;

    float4 av[4], bv[4];
#pragma unroll
    for (int i = 0; i < 4; i++) {
        av[i] = *(const float4*)(Ap + (size_t)(gr + 32 * i) * K + gc);
        bv[i] = *(const float4*)(Bp + (size_t)(gr + 32 * i) * K + gc);
        asm("cvt.rna.tf32.f32 %0, %0;" : "+f"(av[i].x));
        asm("cvt.rna.tf32.f32 %0, %0;" : "+f"(av[i].y));
        asm("cvt.rna.tf32.f32 %0, %0;" : "+f"(av[i].z));
        asm("cvt.rna.tf32.f32 %0, %0;" : "+f"(av[i].w));
    }
#pragma unroll
    for (int i = 0; i < 4; i++) {
        *(float4*)&Abuf[0][(gr + 32 * i) * GPAD + gc] = av[i];
        *(float4*)&Bbuf[0][(gr + 32 * i) * GPAD + gc] = bv[i];
    }
    __syncthreads();

    float acc[4][4][4] = {};
    int nch = K >> 5;
    for (int kt = 0; kt < nch; kt++) {
        int cur = kt & 1;
        if (kt + 1 < nch) {
            int k0 = (kt + 1) << 5;
#pragma unroll
            for (int i = 0; i < 4; i++) {
                av[i] = *(const float4*)(Ap + (size_t)(gr + 32 * i) * K + k0 + gc);
                bv[i] = *(const float4*)(Bp + (size_t)(gr + 32 * i) * K + k0 + gc);
                asm("cvt.rna.tf32.f32 %0, %0;" : "+f"(av[i].x));
                asm("cvt.rna.tf32.f32 %0, %0;" : "+f"(av[i].y));
                asm("cvt.rna.tf32.f32 %0, %0;" : "+f"(av[i].z));
                asm("cvt.rna.tf32.f32 %0, %0;" : "+f"(av[i].w));
            }
        }
        uint32_t aU = smem_u32(Abuf[cur]);
        uint32_t bU = smem_u32(Bbuf[cur]);
#pragma unroll
        for (int ks = 0; ks < 4; ks++) {
            uint32_t kbyte = (uint32_t)ks * 32u;
            uint32_t bfr[2][4];
            ldsm4(bfr[0], bU + boff + kbyte);
            ldsm4(bfr[1], bU + boff + 16u * GPAD * 4u + kbyte);
#pragma unroll
            for (int mt = 0; mt < 4; mt++) {
                uint32_t afr[4];
                ldsm4(afr, aU + aoff + (uint32_t)mt * 16u * GPAD * 4u + kbyte);
#pragma unroll
                for (int nt = 0; nt < 4; nt++)
                    mma_tf32(acc[mt][nt], afr, &bfr[nt >> 1][(nt & 1) * 2]);
            }
        }
        if (kt + 1 < nch) {
            int nxt = cur ^ 1;
#pragma unroll
            for (int i = 0; i < 4; i++) {
                *(float4*)&Abuf[nxt][(gr + 32 * i) * GPAD + gc] = av[i];
                *(float4*)&Bbuf[nxt][(gr + 32 * i) * GPAD + gc] = bv[i];
            }
            __syncthreads();
        }
    }

    int lg = lane >> 2, lt = lane & 3;
#pragma unroll
    for (int mt = 0; mt < 4; mt++) {
        int r1 = by * 128 + m0 + mt * 16 + lg;
#pragma unroll
        for (int nt = 0; nt < 4; nt++) {
            int cb = bx * 128 + n0 + nt * 8 + lt * 2;
            float2 bb = *(const float2*)(bias + cb);
            float2 v0, v1;
            v0.x = acc[mt][nt][0] + bb.x; v0.y = acc[mt][nt][1] + bb.y;
            v1.x = acc[mt][nt][2] + bb.x; v1.y = acc[mt][nt][3] + bb.y;
            if (relu) {
                v0.x = fmaxf(v0.x, 0.f); v0.y = fmaxf(v0.y, 0.f);
                v1.x = fmaxf(v1.x, 0.f); v1.y = fmaxf(v1.y, 0.f);
            }
            *(float2*)(C + (size_t)r1 * N + cb)       = v0;
            *(float2*)(C + (size_t)(r1 + 8) * N + cb) = v1;
        }
    }
}

__global__ __launch_bounds__(256, 2)
void gemm_mma(const float* __restrict__ A, const float* __restrict__ WT,
              const float* __restrict__ bias, float* __restrict__ C,
              int N, int K, int relu)
{
    gemm_mma_core(A, WT, bias, C, N, K, relu, blockIdx.y, blockIdx.x);
}

__global__ __launch_bounds__(256, 2)
void gemm_mma_qkv(const float* __restrict__ A,
                  const float* __restrict__ WTq, const float* __restrict__ bq, float* __restrict__ Q,
                  const float* __restrict__ WTk, const float* __restrict__ bk, float* __restrict__ Kp,
                  const float* __restrict__ WTv, const float* __restrict__ bv, float* __restrict__ V)
{
    const float* W = (blockIdx.z == 0) ? WTq : (blockIdx.z == 1) ? WTk : WTv;
    const float* b = (blockIdx.z == 0) ? bq  : (blockIdx.z == 1) ? bk  : bv;
    float* C       = (blockIdx.z == 0) ? Q   : (blockIdx.z == 1) ? Kp  : V;
    gemm_mma_core(A, W, b, C, Dsz, Dsz, 0, blockIdx.y, blockIdx.x);
}

// ---------------- embedding * sqrt(D) + sinusoidal PE ----------------
__global__ void embed_kernel(const int* __restrict__ ids, const float* __restrict__ emb,
                             float* __restrict__ X)
{
    int row = blockIdx.x;
    int s   = row % Ssz;
    int id  = ids[row];
    const float* e = emb + (size_t)id * Dsz;
    float* x = X + (size_t)row * Dsz;
    const float nl = -logf(10000.0f) / (float)Dsz;
    for (int d = threadIdx.x; d < Dsz; d += blockDim.x) {
        int i = d >> 1;
        float div = expf((float)(2 * i) * nl);
        float ang = (float)s * div;
        float pe  = (d & 1) ? cosf(ang) : sinf(ang);
        x[d] = e[d] * 32.0f + pe;
    }
}

// ---------------- fused flash attention ----------------
#define ATT_SMEM (4*64*65*4)

__global__ __launch_bounds__(256)
void attn_fused(const float* __restrict__ Q, const float* __restrict__ K,
                const float* __restrict__ V, const int* __restrict__ ids,
                float* __restrict__ CTX)
{
    extern __shared__ float smf[];
    float* qs = smf;
    float* ks = smf + 64 * 65;
    float* vs = smf + 2 * 64 * 65;
    float* ps = smf + 3 * 64 * 65;
    __shared__ float padv[64];
    __shared__ float s_l[64];
    __shared__ int s_any;

    int it = blockIdx.x, bh = blockIdx.y;
    int b = bh >> 4, h = bh & 15;
    int i0 = it * 64;
    int tid = threadIdx.x, tx = tid & 15, ty = tid >> 4;

    const float* Qp = Q + ((size_t)(b * Ssz + i0)) * Dsz + h * HDsz;
    for (int i = tid; i < 64 * 64; i += 256) {
        int r = i >> 6, d = i & 63;
        qs[d * 65 + r] = Qp[(size_t)r * Dsz + d];
    }

    float m[4], l[4], acc[4][4];
#pragma unroll
    for (int i = 0; i < 4; i++) {
        m[i] = -1e30f; l[i] = 0.0f;
#pragma unroll
        for (int n = 0; n < 4; n++) acc[i][n] = 0.0f;
    }

    for (int jt = 0; jt <= it; jt++) {
        int j0 = jt * 64;
        const float* Kp = K + ((size_t)(b * Ssz + j0)) * Dsz + h * HDsz;
        const float* Vp = V + ((size_t)(b * Ssz + j0)) * Dsz + h * HDsz;
        for (int i = tid; i < 64 * 64; i += 256) {
            int r = i >> 6, d = i & 63;
            ks[d * 65 + r] = Kp[(size_t)r * Dsz + d];
            vs[r * 65 + d] = Vp[(size_t)r * Dsz + d];
        }
        if (tid < 64)
            padv[tid] = (ids[b * Ssz + j0 + tid] == 0) ? NEG_INF : 0.0f;
        __syncthreads();

        float s[4][4] = {};
#pragma unroll 8
        for (int d = 0; d < HDsz; d++) {
            float a[4], w[4];
#pragma unroll
            for (int i = 0; i < 4; i++) a[i] = qs[d * 65 + ty * 4 + i];
#pragma unroll
            for (int j = 0; j < 4; j++) w[j] = ks[d * 65 + tx * 4 + j];
#pragma unroll
            for (int i = 0; i < 4; i++)
#pragma unroll
                for (int j = 0; j < 4; j++)
                    s[i][j] = fmaf(a[i], w[j], s[i][j]);
        }
        bool diag = (jt == it);
#pragma unroll
        for (int i = 0; i < 4; i++) {
            int ri = i0 + ty * 4 + i;
            float rmax = NEG_INF;
#pragma unroll
            for (int j = 0; j < 4; j++) {
                float v = s[i][j] * 0.125f + padv[tx * 4 + j];
                if (diag && (j0 + tx * 4 + j) > ri) v = NEG_INF;
                s[i][j] = v;
                rmax = fmaxf(rmax, v);
            }
#pragma unroll
            for (int o = 8; o > 0; o >>= 1)
                rmax = fmaxf(rmax, __shfl_xor_sync(0xffffffffu, rmax, o));
            float mn = fmaxf(m[i], fmaxf(rmax, -1e30f));
            float sc = expf(m[i] - mn);
            l[i] *= sc;
#pragma unroll
            for (int n = 0; n < 4; n++) acc[i][n] *= sc;
            float rs = 0.0f;
#pragma unroll
            for (int j = 0; j < 4; j++) {
                float p = expf(s[i][j] - mn);
                s[i][j] = p;
                rs += p;
            }
#pragma unroll
            for (int o = 8; o > 0; o >>= 1)
                rs += __shfl_xor_sync(0xffffffffu, rs, o);
            l[i] += rs;
            m[i] = mn;
        }
#pragma unroll
        for (int i = 0; i < 4; i++)
#pragma unroll
            for (int j = 0; j < 4; j++)
                ps[(tx * 4 + j) * 65 + ty * 4 + i] = s[i][j];
        __syncthreads();
#pragma unroll 8
        for (int kk = 0; kk < 64; kk++) {
            float a[4], w[4];
#pragma unroll
            for (int i = 0; i < 4; i++) a[i] = ps[kk * 65 + ty * 4 + i];
#pragma unroll
            for (int n = 0; n < 4; n++) w[n] = vs[kk * 65 + tx * 4 + n];
#pragma unroll
            for (int i = 0; i < 4; i++)
#pragma unroll
                for (int n = 0; n < 4; n++)
                    acc[i][n] = fmaf(a[i], w[n], acc[i][n]);
        }
        __syncthreads();
    }

    if (tx == 0)
#pragma unroll
        for (int i = 0; i < 4; i++) s_l[ty * 4 + i] = l[i];
    if (tid == 0) s_any = 0;
    __syncthreads();
    if (tid < 64 && s_l[tid] == 0.0f) s_any = 1;
    __syncthreads();

#pragma unroll
    for (int i = 0; i < 4; i++) {
        if (l[i] > 0.0f) {
            float inv = 1.0f / l[i];
            float* o = CTX + ((size_t)(b * Ssz + i0 + ty * 4 + i)) * Dsz + h * HDsz + tx * 4;
#pragma unroll
            for (int n = 0; n < 4; n++) o[n] = acc[i][n] * inv;
        }
    }

    if (s_any) {
        int part = tid >> 6, n = tid & 63;
        const float* Vb = V + ((size_t)(b * Ssz)) * Dsz + h * HDsz;
        float ssum = 0.0f;
        for (int j = part * 128; j < part * 128 + 128; j++)
            ssum += Vb[(size_t)j * Dsz + n];
        ps[tid] = ssum;
        __syncthreads();
        if (tid < 64)
            padv[tid] = (ps[tid] + ps[tid + 64] + ps[tid + 128] + ps[tid + 192]) * (1.0f / 512.0f);
        __syncthreads();
#pragma unroll
        for (int i = 0; i < 4; i++) {
            if (l[i] == 0.0f) {
                float* o = CTX + ((size_t)(b * Ssz + i0 + ty * 4 + i)) * Dsz + h * HDsz + tx * 4;
#pragma unroll
                for (int n2 = 0; n2 < 4; n2++) o[n2] = padv[tx * 4 + n2];
            }
        }
    }
}

// ---------------- X = LayerNorm(X + T) * g + b  (float4 + shuffle reductions) ----------------
__global__ __launch_bounds__(256)
void add_ln(const float* __restrict__ X, const float* __restrict__ T,
            const float* __restrict__ g, const float* __restrict__ bb,
            float* __restrict__ O)
{
    int row = blockIdx.x;
    int t = threadIdx.x, lane = t & 31, wid = t >> 5;
    const float4* x4 = (const float4*)(X + (size_t)row * Dsz);
    const float4* t4 = (const float4*)(T + (size_t)row * Dsz);
    float4 xa = x4[t], ta = t4[t];
    float4 y;
    y.x = xa.x + ta.x; y.y = xa.y + ta.y; y.z = xa.z + ta.z; y.w = xa.w + ta.w;

    __shared__ float wsum[8];
    float s = y.x + y.y + y.z + y.w;
#pragma unroll
    for (int o = 16; o > 0; o >>= 1) s += __shfl_xor_sync(0xffffffffu, s, o);
    if (lane == 0) wsum[wid] = s;
    __syncthreads();
    float tot = wsum[0] + wsum[1] + wsum[2] + wsum[3]
              + wsum[4] + wsum[5] + wsum[6] + wsum[7];
    float mean = tot * (1.0f / Dsz);

    float dx = y.x - mean, dy = y.y - mean, dz = y.z - mean, dw = y.w - mean;
    float ss = dx * dx + dy * dy + dz * dz + dw * dw;
#pragma unroll
    for (int o = 16; o > 0; o >>= 1) ss += __shfl_xor_sync(0xffffffffu, ss, o);
    __syncthreads();               // protect wsum reuse
    if (lane == 0) wsum[wid] = ss;
    __syncthreads();
    float vtot = wsum[0] + wsum[1] + wsum[2] + wsum[3]
               + wsum[4] + wsum[5] + wsum[6] + wsum[7];
    float inv = rsqrtf(vtot * (1.0f / Dsz) + 1e-5f);

    float4 gg = ((const float4*)g)[t];
    float4 bbv = ((const float4*)bb)[t];
    float4 o4;
    o4.x = dx * inv * gg.x + bbv.x;
    o4.y = dy * inv * gg.y + bbv.y;
    o4.z = dz * inv * gg.z + bbv.z;
    o4.w = dw * inv * gg.w + bbv.w;
    ((float4*)(O + (size_t)row * Dsz))[t] = o4;
}

// ---------------- launch ----------------
extern "C" void kernel_launch(void* const* d_in, const int* in_sizes, int n_in,
                              void* d_out, int out_size)
{
    const int*   ids    = (const int*)  d_in[0];
    const float* emb    = (const float*)d_in[2];
    const float* Wq     = (const float*)d_in[3];
    const float* bq     = (const float*)d_in[4];
    const float* Wk     = (const float*)d_in[5];
    const float* bk     = (const float*)d_in[6];
    const float* Wv     = (const float*)d_in[7];
    const float* bv     = (const float*)d_in[8];
    const float* Wo     = (const float*)d_in[9];
    const float* bo     = (const float*)d_in[10];
    const float* g1     = (const float*)d_in[11];
    const float* b1n    = (const float*)d_in[12];
    const float* W1     = (const float*)d_in[13];
    const float* b1f    = (const float*)d_in[14];
    const float* W2     = (const float*)d_in[15];
    const float* b2f    = (const float*)d_in[16];
    const float* g2     = (const float*)d_in[17];
    const float* b2n    = (const float*)d_in[18];
    const float* Wout   = (const float*)d_in[19];
    const float* bout   = (const float*)d_in[20];
    float* out = (float*)d_out;

    float *X, *Q, *K, *V, *CTX, *T, *FF;
    float *WTq, *WTk, *WTv, *WTo, *WT1, *WT2, *WTout;
    cudaGetSymbolAddress((void**)&X,   g_X);
    cudaGetSymbolAddress((void**)&Q,   g_Q);
    cudaGetSymbolAddress((void**)&K,   g_K);
    cudaGetSymbolAddress((void**)&V,   g_V);
    cudaGetSymbolAddress((void**)&CTX, g_CTX);
    cudaGetSymbolAddress((void**)&T,   g_T);
    cudaGetSymbolAddress((void**)&FF,  g_FF);
    cudaGetSymbolAddress((void**)&WTq, g_WTq);
    cudaGetSymbolAddress((void**)&WTk, g_WTk);
    cudaGetSymbolAddress((void**)&WTv, g_WTv);
    cudaGetSymbolAddress((void**)&WTo, g_WTo);
    cudaGetSymbolAddress((void**)&WT1, g_WT1);
    cudaGetSymbolAddress((void**)&WT2, g_WT2);
    cudaGetSymbolAddress((void**)&WTout, g_WTout);

    cudaFuncSetAttribute(gemm_mma,     cudaFuncAttributeMaxDynamicSharedMemorySize, GEMM_SMEM);
    cudaFuncSetAttribute(gemm_mma_qkv, cudaFuncAttributeMaxDynamicSharedMemorySize, GEMM_SMEM);
    cudaFuncSetAttribute(attn_fused,   cudaFuncAttributeMaxDynamicSharedMemorySize, ATT_SMEM);

    // weight transposes (+tf32 rounding), recomputed every replay (deterministic)
    transpose_tf32<<<dim3(Dsz/32, Dsz/32, Lsz), dim3(32, 8)>>>(Wq, WTq, Dsz, Dsz);
    transpose_tf32<<<dim3(Dsz/32, Dsz/32, Lsz), dim3(32, 8)>>>(Wk, WTk, Dsz, Dsz);
    transpose_tf32<<<dim3(Dsz/32, Dsz/32, Lsz), dim3(32, 8)>>>(Wv, WTv, Dsz, Dsz);
    transpose_tf32<<<dim3(Dsz/32, Dsz/32, Lsz), dim3(32, 8)>>>(Wo, WTo, Dsz, Dsz);
    transpose_tf32<<<dim3(Fsz/32, Dsz/32, Lsz), dim3(32, 8)>>>(W1, WT1, Dsz, Fsz);
    transpose_tf32<<<dim3(Dsz/32, Fsz/32, Lsz), dim3(32, 8)>>>(W2, WT2, Fsz, Dsz);
    transpose_tf32<<<dim3(Vsz/32, Dsz/32, 1),   dim3(32, 8)>>>(Wout, WTout, Dsz, Vsz);

    embed_kernel<<<NTOK, 256>>>(ids, emb, X);

    for (int l = 0; l < Lsz; l++) {
        const float* wtq = WTq + (size_t)l * Dsz * Dsz;
        const float* wtk = WTk + (size_t)l * Dsz * Dsz;
        const float* wtv = WTv + (size_t)l * Dsz * Dsz;
        const float* wto = WTo + (size_t)l * Dsz * Dsz;
        const float* wt1 = WT1 + (size_t)l * Dsz * Fsz;
        const float* wt2 = WT2 + (size_t)l * Fsz * Dsz;
        const float* bql = bq + (size_t)l * Dsz;
        const float* bkl = bk + (size_t)l * Dsz;
        const float* bvl = bv + (size_t)l * Dsz;
        const float* bol = bo + (size_t)l * Dsz;
        const float* b1fl = b1f + (size_t)l * Fsz;
        const float* b2fl = b2f + (size_t)l * Dsz;
        const float* g1l = g1 + (size_t)l * Dsz;
        const float* b1nl = b1n + (size_t)l * Dsz;
        const float* g2l = g2 + (size_t)l * Dsz;
        const float* b2nl = b2n + (size_t)l * Dsz;

        gemm_mma_qkv<<<dim3(NTOK/128, Dsz/128, 3), 256, GEMM_SMEM>>>(
            X, wtq, bql, Q, wtk, bkl, K, wtv, bvl, V);

        attn_fused<<<dim3(Ssz/64, Bsz*Hsz), 256, ATT_SMEM>>>(Q, K, V, ids, CTX);

        gemm_mma<<<dim3(NTOK/128, Dsz/128), 256, GEMM_SMEM>>>(CTX, wto, bol, T, Dsz, Dsz, 0);
        add_ln<<<NTOK, 256>>>(X, T, g1l, b1nl, X);

        gemm_mma<<<dim3(NTOK/128, Fsz/128), 256, GEMM_SMEM>>>(X, wt1, b1fl, FF, Fsz, Dsz, 1);
        gemm_mma<<<dim3(NTOK/128, Dsz/128), 256, GEMM_SMEM>>>(FF, wt2, b2fl, T, Dsz, Fsz, 0);
        add_ln<<<NTOK, 256>>>(X, T, g2l, b2nl, X);
    }

    gemm_mma<<<dim3(NTOK/128, Vsz/128), 256, GEMM_SMEM>>>(X, WTout, bout, out, Vsz, Dsz, 0);
}

// round 13
// speedup vs baseline: 1.0535x; 1.0222x over previous
#include <cuda_runtime.h>
#include <cstdint>
#include <math.h>

#define Bsz 4
#define Ssz 512
#define Dsz 1024
#define Hsz 16
#define HDsz 64
#define Lsz 6
#define Fsz 4096
#define Vsz 32000
#define NTOK (Bsz*Ssz)

#define NEG_INF (-1.0f/0.0f)

// ---------------- scratch (no allocation allowed; __device__ globals) ----------------
__device__ float g_X[NTOK*Dsz];
__device__ float g_Q[NTOK*Dsz];
__device__ float g_K[NTOK*Dsz];
__device__ float g_V[NTOK*Dsz];
__device__ float g_CTX[NTOK*Dsz];
__device__ float g_T[NTOK*Dsz];
__device__ float g_FF[(size_t)NTOK*Fsz];
// transposed (tf32-rounded) weights
__device__ float g_WTq[(size_t)Lsz*Dsz*Dsz];
__device__ float g_WTk[(size_t)Lsz*Dsz*Dsz];
__device__ float g_WTv[(size_t)Lsz*Dsz*Dsz];
__device__ float g_WTo[(size_t)Lsz*Dsz*Dsz];
__device__ float g_WT1[(size_t)Lsz*Dsz*Fsz];
__device__ float g_WT2[(size_t)Lsz*Fsz*Dsz];
__device__ float g_WTout[(size_t)Vsz*Dsz];

__device__ __forceinline__ uint32_t smem_u32(const void* p) {
    uint32_t a;
    asm("{ .reg .u64 t; cvta.to.shared.u64 t, %1; cvt.u32.u64 %0, t; }" : "=r"(a) : "l"(p));
    return a;
}

// ================= weight transpose (+ tf32 rounding), 64x64 tiles, MLP=16 =================
// in: [K,N] row-major; out: [N,K] row-major; blockIdx.z = matrix index (layer)
__global__ __launch_bounds__(256)
void transpose_tf32(const float* __restrict__ in, float* __restrict__ out,
                    int K, int N)
{
    __shared__ float tile[64][65];
    size_t off = (size_t)blockIdx.z * K * N;
    in += off; out += off;
    int t = threadIdx.x;
    int c = t & 63;                 // column within tile (lane-contiguous)
    int r0 = t >> 6;                // 0..3
    int k0 = blockIdx.y * 64, n0 = blockIdx.x * 64;
    const float* ip = in + (size_t)k0 * N + n0 + c;
#pragma unroll
    for (int i = 0; i < 16; i++) {
        int r = r0 + i * 4;
        tile[r][c] = ip[(size_t)r * N];     // 16 independent loads in flight
    }
    __syncthreads();
    float* op = out + (size_t)n0 * K + k0 + c;
#pragma unroll
    for (int i = 0; i < 16; i++) {
        int r = r0 + i * 4;
        float v = tile[c][r];               // (c + r) mod 32 distinct -> conflict-free
        asm("cvt.rna.tf32.f32 %0, %0;" : "+f"(v));
        op[(size_t)r * K] = v;
    }
}

// ================= tf32 mma.sync GEMM (R8 proven core, 128x128) =================
#define GPAD 36
#define GEMM_SMEM (4*128*GPAD*4)

__device__ __forceinline__ void mma_tf32(float* d, const uint32_t* a, const uint32_t* b)
{
    asm volatile("mma.sync.aligned.m16n8k8.row.col.f32.tf32.tf32.f32 "
        "{%0,%1,%2,%3}, {%4,%5,%6,%7}, {%8,%9}, {%0,%1,%2,%3};"
        : "+f"(d[0]), "+f"(d[1]), "+f"(d[2]), "+f"(d[3])
        : "r"(a[0]), "r"(a[1]), "r"(a[2]), "r"(a[3]), "r"(b[0]), "r"(b[1]));
}

__device__ __forceinline__ void ldsm4(uint32_t* r, uint32_t addr)
{
    asm volatile("ldmatrix.sync.aligned.m8n8.x4.shared.b16 {%0,%1,%2,%3}, [%4];"
        : "=r"(r[0]), "=r"(r[1]), "=r"(r[2]), "=r"(r[3]) : "r"(addr));
}

__device__ __forceinline__ void gemm_mma_core(const float* __restrict__ A,
        const float* __restrict__ WT, const float* __restrict__ bias,
        float* __restrict__ C, int N, int K, int relu, int bx, int by)
{
    extern __shared__ float sm[];
    float* Abuf[2] = { sm,              sm + 2 * 128 * GPAD };
    float* Bbuf[2] = { sm + 128 * GPAD, sm + 3 * 128 * GPAD };

    int tid = threadIdx.x, lane = tid & 31, wid = tid >> 5;
    int m0 = (wid & 1) * 64;
    int n0 = (wid >> 1) * 32;

    const float* Ap = A  + (size_t)(by * 128) * K;
    const float* Bp = WT + (size_t)(bx * 128) * K;

    int gr = tid >> 3;
    int gc = (tid & 7) * 4;

    uint32_t aoff = ((uint32_t)(m0 + (lane & 15)) * GPAD + ((lane >> 4) << 2)) * 4u;
    uint32_t boff = ((uint32_t)(n0 + ((lane >> 4) << 3) + (lane & 7)) * GPAD
                     + (((lane >> 3) & 1) << 2)) * 4u;

    float4 av[4], bv[4];
#pragma unroll
    for (int i = 0; i < 4; i++) {
        av[i] = *(const float4*)(Ap + (size_t)(gr + 32 * i) * K + gc);
        bv[i] = *(const float4*)(Bp + (size_t)(gr + 32 * i) * K + gc);
        asm("cvt.rna.tf32.f32 %0, %0;" : "+f"(av[i].x));
        asm("cvt.rna.tf32.f32 %0, %0;" : "+f"(av[i].y));
        asm("cvt.rna.tf32.f32 %0, %0;" : "+f"(av[i].z));
        asm("cvt.rna.tf32.f32 %0, %0;" : "+f"(av[i].w));
    }
#pragma unroll
    for (int i = 0; i < 4; i++) {
        *(float4*)&Abuf[0][(gr + 32 * i) * GPAD + gc] = av[i];
        *(float4*)&Bbuf[0][(gr + 32 * i) * GPAD + gc] = bv[i];
    }
    __syncthreads();

    float acc[4][4][4] = {};
    int nch = K >> 5;
    for (int kt = 0; kt < nch; kt++) {
        int cur = kt & 1;
        if (kt + 1 < nch) {
            int k0 = (kt + 1) << 5;
#pragma unroll
            for (int i = 0; i < 4; i++) {
                av[i] = *(const float4*)(Ap + (size_t)(gr + 32 * i) * K + k0 + gc);
                bv[i] = *(const float4*)(Bp + (size_t)(gr + 32 * i) * K + k0 + gc);
                asm("cvt.rna.tf32.f32 %0, %0;" : "+f"(av[i].x));
                asm("cvt.rna.tf32.f32 %0, %0;" : "+f"(av[i].y));
                asm("cvt.rna.tf32.f32 %0, %0;" : "+f"(av[i].z));
                asm("cvt.rna.tf32.f32 %0, %0;" : "+f"(av[i].w));
            }
        }
        uint32_t aU = smem_u32(Abuf[cur]);
        uint32_t bU = smem_u32(Bbuf[cur]);
#pragma unroll
        for (int ks = 0; ks < 4; ks++) {
            uint32_t kbyte = (uint32_t)ks * 32u;
            uint32_t bfr[2][4];
            ldsm4(bfr[0], bU + boff + kbyte);
            ldsm4(bfr[1], bU + boff + 16u * GPAD * 4u + kbyte);
#pragma unroll
            for (int mt = 0; mt < 4; mt++) {
                uint32_t afr[4];
                ldsm4(afr, aU + aoff + (uint32_t)mt * 16u * GPAD * 4u + kbyte);
#pragma unroll
                for (int nt = 0; nt < 4; nt++)
                    mma_tf32(acc[mt][nt], afr, &bfr[nt >> 1][(nt & 1) * 2]);
            }
        }
        if (kt + 1 < nch) {
            int nxt = cur ^ 1;
#pragma unroll
            for (int i = 0; i < 4; i++) {
                *(float4*)&Abuf[nxt][(gr + 32 * i) * GPAD + gc] = av[i];
                *(float4*)&Bbuf[nxt][(gr + 32 * i) * GPAD + gc] = bv[i];
            }
            __syncthreads();
        }
    }

    int lg = lane >> 2, lt = lane & 3;
#pragma unroll
    for (int mt = 0; mt < 4; mt++) {
        int r1 = by * 128 + m0 + mt * 16 + lg;
#pragma unroll
        for (int nt = 0; nt < 4; nt++) {
            int cb = bx * 128 + n0 + nt * 8 + lt * 2;
            float2 bb = *(const float2*)(bias + cb);
            float2 v0, v1;
            v0.x = acc[mt][nt][0] + bb.x; v0.y = acc[mt][nt][1] + bb.y;
            v1.x = acc[mt][nt][2] + bb.x; v1.y = acc[mt][nt][3] + bb.y;
            if (relu) {
                v0.x = fmaxf(v0.x, 0.f); v0.y = fmaxf(v0.y, 0.f);
                v1.x = fmaxf(v1.x, 0.f); v1.y = fmaxf(v1.y, 0.f);
            }
            *(float2*)(C + (size_t)r1 * N + cb)       = v0;
            *(float2*)(C + (size_t)(r1 + 8) * N + cb) = v1;
        }
    }
}

__global__ __launch_bounds__(256, 2)
void gemm_mma(const float* __restrict__ A, const float* __restrict__ WT,
              const float* __restrict__ bias, float* __restrict__ C,
              int N, int K, int relu)
{
    gemm_mma_core(A, WT, bias, C, N, K, relu, blockIdx.y, blockIdx.x);
}

__global__ __launch_bounds__(256, 2)
void gemm_mma_qkv(const float* __restrict__ A,
                  const float* __restrict__ WTq, const float* __restrict__ bq, float* __restrict__ Q,
                  const float* __restrict__ WTk, const float* __restrict__ bk, float* __restrict__ Kp,
                  const float* __restrict__ WTv, const float* __restrict__ bv, float* __restrict__ V)
{
    const float* W = (blockIdx.z == 0) ? WTq : (blockIdx.z == 1) ? WTk : WTv;
    const float* b = (blockIdx.z == 0) ? bq  : (blockIdx.z == 1) ? bk  : bv;
    float* C       = (blockIdx.z == 0) ? Q   : (blockIdx.z == 1) ? Kp  : V;
    gemm_mma_core(A, W, b, C, Dsz, Dsz, 0, blockIdx.y, blockIdx.x);
}

// ---------------- embedding * sqrt(D) + sinusoidal PE ----------------
__global__ void embed_kernel(const int* __restrict__ ids, const float* __restrict__ emb,
                             float* __restrict__ X)
{
    int row = blockIdx.x;
    int s   = row % Ssz;
    int id  = ids[row];
    const float* e = emb + (size_t)id * Dsz;
    float* x = X + (size_t)row * Dsz;
    const float nl = -logf(10000.0f) / (float)Dsz;
    for (int d = threadIdx.x; d < Dsz; d += blockDim.x) {
        int i = d >> 1;
        float div = expf((float)(2 * i) * nl);
        float ang = (float)s * div;
        float pe  = (d & 1) ? cosf(ang) : sinf(ang);
        x[d] = e[d] * 32.0f + pe;
    }
}

// ---------------- fused flash attention ----------------
#define ATT_SMEM (4*64*65*4)

__global__ __launch_bounds__(256)
void attn_fused(const float* __restrict__ Q, const float* __restrict__ K,
                const float* __restrict__ V, const int* __restrict__ ids,
                float* __restrict__ CTX)
{
    extern __shared__ float smf[];
    float* qs = smf;
    float* ks = smf + 64 * 65;
    float* vs = smf + 2 * 64 * 65;
    float* ps = smf + 3 * 64 * 65;
    __shared__ float padv[64];
    __shared__ float s_l[64];
    __shared__ int s_any;

    int it = blockIdx.x, bh = blockIdx.y;
    int b = bh >> 4, h = bh & 15;
    int i0 = it * 64;
    int tid = threadIdx.x, tx = tid & 15, ty = tid >> 4;

    const float* Qp = Q + ((size_t)(b * Ssz + i0)) * Dsz + h * HDsz;
    for (int i = tid; i < 64 * 64; i += 256) {
        int r = i >> 6, d = i & 63;
        qs[d * 65 + r] = Qp[(size_t)r * Dsz + d];
    }

    float m[4], l[4], acc[4][4];
#pragma unroll
    for (int i = 0; i < 4; i++) {
        m[i] = -1e30f; l[i] = 0.0f;
#pragma unroll
        for (int n = 0; n < 4; n++) acc[i][n] = 0.0f;
    }

    for (int jt = 0; jt <= it; jt++) {
        int j0 = jt * 64;
        const float* Kp = K + ((size_t)(b * Ssz + j0)) * Dsz + h * HDsz;
        const float* Vp = V + ((size_t)(b * Ssz + j0)) * Dsz + h * HDsz;
        for (int i = tid; i < 64 * 64; i += 256) {
            int r = i >> 6, d = i & 63;
            ks[d * 65 + r] = Kp[(size_t)r * Dsz + d];
            vs[r * 65 + d] = Vp[(size_t)r * Dsz + d];
        }
        if (tid < 64)
            padv[tid] = (ids[b * Ssz + j0 + tid] == 0) ? NEG_INF : 0.0f;
        __syncthreads();

        float s[4][4] = {};
#pragma unroll 8
        for (int d = 0; d < HDsz; d++) {
            float a[4], w[4];
#pragma unroll
            for (int i = 0; i < 4; i++) a[i] = qs[d * 65 + ty * 4 + i];
#pragma unroll
            for (int j = 0; j < 4; j++) w[j] = ks[d * 65 + tx * 4 + j];
#pragma unroll
            for (int i = 0; i < 4; i++)
#pragma unroll
                for (int j = 0; j < 4; j++)
                    s[i][j] = fmaf(a[i], w[j], s[i][j]);
        }
        bool diag = (jt == it);
#pragma unroll
        for (int i = 0; i < 4; i++) {
            int ri = i0 + ty * 4 + i;
            float rmax = NEG_INF;
#pragma unroll
            for (int j = 0; j < 4; j++) {
                float v = s[i][j] * 0.125f + padv[tx * 4 + j];
                if (diag && (j0 + tx * 4 + j) > ri) v = NEG_INF;
                s[i][j] = v;
                rmax = fmaxf(rmax, v);
            }
#pragma unroll
            for (int o = 8; o > 0; o >>= 1)
                rmax = fmaxf(rmax, __shfl_xor_sync(0xffffffffu, rmax, o));
            float mn = fmaxf(m[i], fmaxf(rmax, -1e30f));
            float sc = expf(m[i] - mn);
            l[i] *= sc;
#pragma unroll
            for (int n = 0; n < 4; n++) acc[i][n] *= sc;
            float rs = 0.0f;
#pragma unroll
            for (int j = 0; j < 4; j++) {
                float p = expf(s[i][j] - mn);
                s[i][j] = p;
                rs += p;
            }
#pragma unroll
            for (int o = 8; o > 0; o >>= 1)
                rs += __shfl_xor_sync(0xffffffffu, rs, o);
            l[i] += rs;
            m[i] = mn;
        }
#pragma unroll
        for (int i = 0; i < 4; i++)
#pragma unroll
            for (int j = 0; j < 4; j++)
                ps[(tx * 4 + j) * 65 + ty * 4 + i] = s[i][j];
        __syncthreads();
#pragma unroll 8
        for (int kk = 0; kk < 64; kk++) {
            float a[4], w[4];
#pragma unroll
            for (int i = 0; i < 4; i++) a[i] = ps[kk * 65 + ty * 4 + i];
#pragma unroll
            for (int n = 0; n < 4; n++) w[n] = vs[kk * 65 + tx * 4 + n];
#pragma unroll
            for (int i = 0; i < 4; i++)
#pragma unroll
                for (int n = 0; n < 4; n++)
                    acc[i][n] = fmaf(a[i], w[n], acc[i][n]);
        }
        __syncthreads();
    }

    if (tx == 0)
#pragma unroll
        for (int i = 0; i < 4; i++) s_l[ty * 4 + i] = l[i];
    if (tid == 0) s_any = 0;
    __syncthreads();
    if (tid < 64 && s_l[tid] == 0.0f) s_any = 1;
    __syncthreads();

#pragma unroll
    for (int i = 0; i < 4; i++) {
        if (l[i] > 0.0f) {
            float inv = 1.0f / l[i];
            float* o = CTX + ((size_t)(b * Ssz + i0 + ty * 4 + i)) * Dsz + h * HDsz + tx * 4;
#pragma unroll
            for (int n = 0; n < 4; n++) o[n] = acc[i][n] * inv;
        }
    }

    if (s_any) {
        int part = tid >> 6, n = tid & 63;
        const float* Vb = V + ((size_t)(b * Ssz)) * Dsz + h * HDsz;
        float ssum = 0.0f;
        for (int j = part * 128; j < part * 128 + 128; j++)
            ssum += Vb[(size_t)j * Dsz + n];
        ps[tid] = ssum;
        __syncthreads();
        if (tid < 64)
            padv[tid] = (ps[tid] + ps[tid + 64] + ps[tid + 128] + ps[tid + 192]) * (1.0f / 512.0f);
        __syncthreads();
#pragma unroll
        for (int i = 0; i < 4; i++) {
            if (l[i] == 0.0f) {
                float* o = CTX + ((size_t)(b * Ssz + i0 + ty * 4 + i)) * Dsz + h * HDsz + tx * 4;
#pragma unroll
                for (int n2 = 0; n2 < 4; n2++) o[n2] = padv[tx * 4 + n2];
            }
        }
    }
}

// ---------------- X = LayerNorm(X + T) * g + b  (float4 + shuffle reductions) ----------------
__global__ __launch_bounds__(256)
void add_ln(const float* __restrict__ X, const float* __restrict__ T,
            const float* __restrict__ g, const float* __restrict__ bb,
            float* __restrict__ O)
{
    int row = blockIdx.x;
    int t = threadIdx.x, lane = t & 31, wid = t >> 5;
    const float4* x4 = (const float4*)(X + (size_t)row * Dsz);
    const float4* t4 = (const float4*)(T + (size_t)row * Dsz);
    float4 xa = x4[t], ta = t4[t];
    float4 y;
    y.x = xa.x + ta.x; y.y = xa.y + ta.y; y.z = xa.z + ta.z; y.w = xa.w + ta.w;

    __shared__ float wsum[8];
    float s = y.x + y.y + y.z + y.w;
#pragma unroll
    for (int o = 16; o > 0; o >>= 1) s += __shfl_xor_sync(0xffffffffu, s, o);
    if (lane == 0) wsum[wid] = s;
    __syncthreads();
    float tot = wsum[0] + wsum[1] + wsum[2] + wsum[3]
              + wsum[4] + wsum[5] + wsum[6] + wsum[7];
    float mean = tot * (1.0f / Dsz);

    float dx = y.x - mean, dy = y.y - mean, dz = y.z - mean, dw = y.w - mean;
    float ss = dx * dx + dy * dy + dz * dz + dw * dw;
#pragma unroll
    for (int o = 16; o > 0; o >>= 1) ss += __shfl_xor_sync(0xffffffffu, ss, o);
    __syncthreads();               // protect wsum reuse
    if (lane == 0) wsum[wid] = ss;
    __syncthreads();
    float vtot = wsum[0] + wsum[1] + wsum[2] + wsum[3]
               + wsum[4] + wsum[5] + wsum[6] + wsum[7];
    float inv = rsqrtf(vtot * (1.0f / Dsz) + 1e-5f);

    float4 gg = ((const float4*)g)[t];
    float4 bbv = ((const float4*)bb)[t];
    float4 o4;
    o4.x = dx * inv * gg.x + bbv.x;
    o4.y = dy * inv * gg.y + bbv.y;
    o4.z = dz * inv * gg.z + bbv.z;
    o4.w = dw * inv * gg.w + bbv.w;
    ((float4*)(O + (size_t)row * Dsz))[t] = o4;
}

// ---------------- launch ----------------
extern "C" void kernel_launch(void* const* d_in, const int* in_sizes, int n_in,
                              void* d_out, int out_size)
{
    const int*   ids    = (const int*)  d_in[0];
    const float* emb    = (const float*)d_in[2];
    const float* Wq     = (const float*)d_in[3];
    const float* bq     = (const float*)d_in[4];
    const float* Wk     = (const float*)d_in[5];
    const float* bk     = (const float*)d_in[6];
    const float* Wv     = (const float*)d_in[7];
    const float* bv     = (const float*)d_in[8];
    const float* Wo     = (const float*)d_in[9];
    const float* bo     = (const float*)d_in[10];
    const float* g1     = (const float*)d_in[11];
    const float* b1n    = (const float*)d_in[12];
    const float* W1     = (const float*)d_in[13];
    const float* b1f    = (const float*)d_in[14];
    const float* W2     = (const float*)d_in[15];
    const float* b2f    = (const float*)d_in[16];
    const float* g2     = (const float*)d_in[17];
    const float* b2n    = (const float*)d_in[18];
    const float* Wout   = (const float*)d_in[19];
    const float* bout   = (const float*)d_in[20];
    float* out = (float*)d_out;

    float *X, *Q, *K, *V, *CTX, *T, *FF;
    float *WTq, *WTk, *WTv, *WTo, *WT1, *WT2, *WTout;
    cudaGetSymbolAddress((void**)&X,   g_X);
    cudaGetSymbolAddress((void**)&Q,   g_Q);
    cudaGetSymbolAddress((void**)&K,   g_K);
    cudaGetSymbolAddress((void**)&V,   g_V);
    cudaGetSymbolAddress((void**)&CTX, g_CTX);
    cudaGetSymbolAddress((void**)&T,   g_T);
    cudaGetSymbolAddress((void**)&FF,  g_FF);
    cudaGetSymbolAddress((void**)&WTq, g_WTq);
    cudaGetSymbolAddress((void**)&WTk, g_WTk);
    cudaGetSymbolAddress((void**)&WTv, g_WTv);
    cudaGetSymbolAddress((void**)&WTo, g_WTo);
    cudaGetSymbolAddress((void**)&WT1, g_WT1);
    cudaGetSymbolAddress((void**)&WT2, g_WT2);
    cudaGetSymbolAddress((void**)&WTout, g_WTout);

    cudaFuncSetAttribute(gemm_mma,     cudaFuncAttributeMaxDynamicSharedMemorySize, GEMM_SMEM);
    cudaFuncSetAttribute(gemm_mma_qkv, cudaFuncAttributeMaxDynamicSharedMemorySize, GEMM_SMEM);
    cudaFuncSetAttribute(attn_fused,   cudaFuncAttributeMaxDynamicSharedMemorySize, ATT_SMEM);

    // weight transposes (+tf32 rounding), recomputed every replay (deterministic)
    transpose_tf32<<<dim3(Dsz/64, Dsz/64, Lsz), 256>>>(Wq, WTq, Dsz, Dsz);
    transpose_tf32<<<dim3(Dsz/64, Dsz/64, Lsz), 256>>>(Wk, WTk, Dsz, Dsz);
    transpose_tf32<<<dim3(Dsz/64, Dsz/64, Lsz), 256>>>(Wv, WTv, Dsz, Dsz);
    transpose_tf32<<<dim3(Dsz/64, Dsz/64, Lsz), 256>>>(Wo, WTo, Dsz, Dsz);
    transpose_tf32<<<dim3(Fsz/64, Dsz/64, Lsz), 256>>>(W1, WT1, Dsz, Fsz);
    transpose_tf32<<<dim3(Dsz/64, Fsz/64, Lsz), 256>>>(W2, WT2, Fsz, Dsz);
    transpose_tf32<<<dim3(Vsz/64, Dsz/64, 1),   256>>>(Wout, WTout, Dsz, Vsz);

    embed_kernel<<<NTOK, 256>>>(ids, emb, X);

    for (int l = 0; l < Lsz; l++) {
        const float* wtq = WTq + (size_t)l * Dsz * Dsz;
        const float* wtk = WTk + (size_t)l * Dsz * Dsz;
        const float* wtv = WTv + (size_t)l * Dsz * Dsz;
        const float* wto = WTo + (size_t)l * Dsz * Dsz;
        const float* wt1 = WT1 + (size_t)l * Dsz * Fsz;
        const float* wt2 = WT2 + (size_t)l * Fsz * Dsz;
        const float* bql = bq + (size_t)l * Dsz;
        const float* bkl = bk + (size_t)l * Dsz;
        const float* bvl = bv + (size_t)l * Dsz;
        const float* bol = bo + (size_t)l * Dsz;
        const float* b1fl = b1f + (size_t)l * Fsz;
        const float* b2fl = b2f + (size_t)l * Dsz;
        const float* g1l = g1 + (size_t)l * Dsz;
        const float* b1nl = b1n + (size_t)l * Dsz;
        const float* g2l = g2 + (size_t)l * Dsz;
        const float* b2nl = b2n + (size_t)l * Dsz;

        gemm_mma_qkv<<<dim3(NTOK/128, Dsz/128, 3), 256, GEMM_SMEM>>>(
            X, wtq, bql, Q, wtk, bkl, K, wtv, bvl, V);

        attn_fused<<<dim3(Ssz/64, Bsz*Hsz), 256, ATT_SMEM>>>(Q, K, V, ids, CTX);

        gemm_mma<<<dim3(NTOK/128, Dsz/128), 256, GEMM_SMEM>>>(CTX, wto, bol, T, Dsz, Dsz, 0);
        add_ln<<<NTOK, 256>>>(X, T, g1l, b1nl, X);

        gemm_mma<<<dim3(NTOK/128, Fsz/128), 256, GEMM_SMEM>>>(X, wt1, b1fl, FF, Fsz, Dsz, 1);
        gemm_mma<<<dim3(NTOK/128, Dsz/128), 256, GEMM_SMEM>>>(FF, wt2, b2fl, T, Dsz, Fsz, 0);
        add_ln<<<NTOK, 256>>>(X, T, g2l, b2nl, X);
    }

    gemm_mma<<<dim3(NTOK/128, Vsz/128), 256, GEMM_SMEM>>>(X, WTout, bout, out, Vsz, Dsz, 0);
}